// round 17
// baseline (speedup 1.0000x reference)
#include <cuda_runtime.h>
#include <cstdint>

// MaskedNormalize, round 13: per-batch L2 pipelined persistent kernel.
// x [16, 4, 1024, 1024] fp32. valid = (x != 0).
// Invalid entries are exactly 0 => sum(x*v)=sum(x), sum(x^2*v)=sum(x^2);
// only the count needs the predicate.
//
// Key idea: one batch = 16 MB << 126 MB L2. Process batches sequentially
// with a 1-deep software pipeline:
//     reduce(0); arrive(0)
//     for i: { reduce(i+1); arrive(i+1) }  wait(i); stats(i); normalize(i)
// normalize(i) reads data that was DRAM-fetched one step earlier and is
// still L2-resident -> DRAM traffic drops from 768 MB to ~512 MB.
// The per-batch barrier wait is hidden behind reduce(i+1).
//
// 296 persistent blocks (2 per SM) x 512 threads, all co-resident -> the
// per-batch spin barriers are deadlock-free. Monotonic per-batch arrival
// counters (never reset; graph replays serialize, each launch contributes
// exactly GRID arrivals per counter).

#define BATCHES     16
#define PER_BATCH   (4u * 1024u * 1024u)     // elements per batch
#define VEC_PER_B   (PER_BATCH / 4u)         // float4 per batch = 1,048,576

#define GRID        296                      // 2 blocks per SM (148 SMs)
#define THREADS     512

#define CHUNK_BASE  (VEC_PER_B / GRID)       // 3542
#define CHUNK_REM   (VEC_PER_B % GRID)       // 144

#define EPS         1e-5f

// Deterministic scratch: every slot written every launch.
__device__ float g_s1[BATCHES][GRID];
__device__ float g_s2[BATCHES][GRID];
__device__ float g_cn[BATCHES][GRID];
// Monotonic per-batch arrival counters; never reset.
__device__ unsigned long long g_arr[BATCHES];

__global__ __launch_bounds__(THREADS) void mn_pipe_kernel(const float* __restrict__ x,
                                                          float* __restrict__ out)
{
    const int bid  = blockIdx.x;
    const int tid  = threadIdx.x;
    const int lane = tid & 31;
    const int wid  = tid >> 5;

    // This block's chunk (same offsets within every batch).
    const unsigned start = (unsigned)bid * CHUNK_BASE + (unsigned)min(bid, CHUNK_REM);
    const unsigned count = CHUNK_BASE + (bid < CHUNK_REM ? 1u : 0u);

    __shared__ float  sw1[THREADS / 32];
    __shared__ float  sw2[THREADS / 32];
    __shared__ int    swc[THREADS / 32];
    __shared__ double d1[512], d2[512], dc[512];
    __shared__ float2 sh_stats;

    // ---- helper lambdas ----------------------------------------------------
    auto reduce_batch = [&](int i) {
        const float4* __restrict__ xb =
            reinterpret_cast<const float4*>(x + (size_t)i * PER_BATCH) + start;

        float s1 = 0.f, s2 = 0.f;
        int   cnt = 0;
        #pragma unroll 4
        for (unsigned j = tid; j < count; j += THREADS) {
            float4 v = xb[j];
            s1  += (v.x + v.y) + (v.z + v.w);
            s2  += (v.x * v.x + v.y * v.y) + (v.z * v.z + v.w * v.w);
            cnt += (v.x != 0.f) + (v.y != 0.f) + (v.z != 0.f) + (v.w != 0.f);
        }
        #pragma unroll
        for (int off = 16; off > 0; off >>= 1) {
            s1  += __shfl_xor_sync(0xFFFFFFFFu, s1, off);
            s2  += __shfl_xor_sync(0xFFFFFFFFu, s2, off);
            cnt += __shfl_xor_sync(0xFFFFFFFFu, cnt, off);
        }
        if (lane == 0) { sw1[wid] = s1; sw2[wid] = s2; swc[wid] = cnt; }
        __syncthreads();
        if (wid == 0) {
            s1  = (lane < THREADS / 32) ? sw1[lane] : 0.f;
            s2  = (lane < THREADS / 32) ? sw2[lane] : 0.f;
            cnt = (lane < THREADS / 32) ? swc[lane] : 0;
            #pragma unroll
            for (int off = 8; off > 0; off >>= 1) {
                s1  += __shfl_xor_sync(0xFFFFFFFFu, s1, off);
                s2  += __shfl_xor_sync(0xFFFFFFFFu, s2, off);
                cnt += __shfl_xor_sync(0xFFFFFFFFu, cnt, off);
            }
            if (lane == 0) {
                g_s1[i][bid] = s1;
                g_s2[i][bid] = s2;
                g_cn[i][bid] = (float)cnt;
                __threadfence();
                unsigned long long my = atomicAdd(&g_arr[i], 1ULL);
                // stash target for the wait: all 296 arrivals of THIS launch
                // share the same epoch k = my / GRID.
                sw1[0] = __uint_as_float((unsigned)(my / GRID));
            }
        }
        __syncthreads();
    };

    auto wait_and_stats = [&](int i, unsigned epoch_hint) {
        if (tid == 0) {
            unsigned long long target =
                ((unsigned long long)epoch_hint + 1ULL) * (unsigned long long)GRID;
            for (;;) {
                unsigned long long cur;
                asm volatile("ld.global.acquire.gpu.u64 %0, [%1];"
                             : "=l"(cur) : "l"(&g_arr[i]));
                if (cur >= target) break;
            }
        }
        __syncthreads();

        // All partials of batch i visible: redundant per-block stats.
        d1[tid] = (tid < GRID) ? (double)g_s1[i][tid] : 0.0;
        d2[tid] = (tid < GRID) ? (double)g_s2[i][tid] : 0.0;
        dc[tid] = (tid < GRID) ? (double)g_cn[i][tid] : 0.0;
        __syncthreads();
        #pragma unroll
        for (int off = 256; off > 0; off >>= 1) {
            if (tid < off) {
                d1[tid] += d1[tid + off];
                d2[tid] += d2[tid + off];
                dc[tid] += dc[tid + off];
            }
            __syncthreads();
        }
        if (tid == 0) {
            double S1 = d1[0], S2 = d2[0], n = dc[0];
            double mean = S1 / n;
            double var  = (S2 - S1 * S1 / n) / (n - 1.0);
            float  rstd = 1.0f / (sqrtf((float)var) + EPS);
            sh_stats = make_float2((float)mean, rstd);
        }
        __syncthreads();
    };

    auto normalize_batch = [&](int i) {
        const float mean = sh_stats.x;
        const float rstd = sh_stats.y;
        const float4* __restrict__ xb =
            reinterpret_cast<const float4*>(x + (size_t)i * PER_BATCH) + start;
        float4* __restrict__ ob =
            reinterpret_cast<float4*>(out + (size_t)i * PER_BATCH) + start;

        #pragma unroll 4
        for (unsigned j = tid; j < count; j += THREADS) {
            float4 v = xb[j];
            float4 o;
            o.x = (v.x != 0.f) ? (v.x - mean) * rstd : 0.f;
            o.y = (v.y != 0.f) ? (v.y - mean) * rstd : 0.f;
            o.z = (v.z != 0.f) ? (v.z - mean) * rstd : 0.f;
            o.w = (v.w != 0.f) ? (v.w - mean) * rstd : 0.f;
            ob[j] = o;
        }
    };

    // ---- pipelined main loop ------------------------------------------------
    unsigned epoch[BATCHES];

    reduce_batch(0);
    epoch[0] = __float_as_uint(sw1[0]);   // epoch published by reduce_batch
    __syncthreads();

    for (int i = 0; i < BATCHES; i++) {
        if (i + 1 < BATCHES) {
            reduce_batch(i + 1);          // hides the wait for batch i
            epoch[i + 1] = __float_as_uint(sw1[0]);
            __syncthreads();
        }
        wait_and_stats(i, epoch[i]);
        normalize_batch(i);
    }
}

extern "C" void kernel_launch(void* const* d_in, const int* in_sizes, int n_in,
                              void* d_out, int out_size)
{
    const float* x   = (const float*)d_in[0];
    float*       out = (float*)d_out;
    mn_pipe_kernel<<<GRID, THREADS>>>(x, out);
}